// round 3
// baseline (speedup 1.0000x reference)
#include <cuda_runtime.h>

#define GG  49
#define HP  51
#define HID 150
#define BB  128
#define CC  2
#define AA  8
#define KK  30

// ---------------- scratch (static device globals; no allocation) ----------------
__device__ float g_h1[BB * HID * GG * GG];        // 46.1M floats
__device__ float g_h2[BB * HID * GG * GG];        // 46.1M floats
__device__ float g_sT[BB * AA * 9 * HP * HP];     // 24.0M floats
__device__ float g_reward[BB * HP * HP];
__device__ float g_qc[BB * AA * GG * GG];

// ---------------- conv1: grid[B,2,49,49] -> relu -> h1[B,150,49,49] ----------------
__global__ __launch_bounds__(256) void conv1_kernel(const float* __restrict__ gin,
                                                    const float* __restrict__ w,
                                                    const float* __restrict__ bias) {
    int b = blockIdx.y;
    int r0 = blockIdx.x * 7;
    __shared__ float tile[CC * 9 * 51];     // input rows r0-1..r0+7, cols -1..49
    __shared__ float ws[HID * 18];
    __shared__ float bs[HID];
    int tid = threadIdx.x;

    for (int i = tid; i < CC * 9 * 51; i += 256) {
        int ci = i / (9 * 51);
        int rr = (i / 51) % 9;
        int cc = i % 51;
        int gr = r0 + rr - 1, gc = cc - 1;
        float v = 0.f;
        if (gr >= 0 && gr < GG && gc >= 0 && gc < GG)
            v = gin[(b * CC + ci) * GG * GG + gr * GG + gc];
        tile[i] = v;
    }
    for (int i = tid; i < HID * 18; i += 256) ws[i] = w[i];
    for (int i = tid; i < HID; i += 256) bs[i] = bias[i];
    __syncthreads();

    for (int pp = tid; pp < 7 * GG; pp += 256) {
        int lr = pp / GG, lc = pp % GG;
        int gr = r0 + lr;
        if (gr >= GG) continue;
        float patch[18];
#pragma unroll
        for (int ci = 0; ci < CC; ci++)
#pragma unroll
            for (int k = 0; k < 9; k++)
                patch[ci * 9 + k] = tile[ci * 9 * 51 + (lr + k / 3) * 51 + (lc + k % 3)];
        for (int co = 0; co < HID; co++) {
            float a = bs[co];
            const float2* wp = (const float2*)&ws[co * 18];
#pragma unroll
            for (int j = 0; j < 9; j++) {
                float2 w2 = wp[j];
                a = fmaf(patch[2 * j], w2.x, a);
                a = fmaf(patch[2 * j + 1], w2.y, a);
            }
            g_h1[(b * HID + co) * GG * GG + gr * GG + lc] = fmaxf(a, 0.f);
        }
    }
}

// ---------------- conv2: h1 -> relu -> h2  (the 125 GFLOP one) ----------------
// CTA: (5-row chunk, 50-channel chunk, batch). 245 active threads = 5x49 pixels.
__global__ __launch_bounds__(256) void conv2_kernel(const float* __restrict__ w,
                                                    const float* __restrict__ bias) {
    int b = blockIdx.z;
    int cob = blockIdx.y * 50;
    int r0 = blockIdx.x * 5;
    __shared__ float tile[7 * 51];
    __shared__ float ws[9 * 52];            // [k][co], stride 52 for 8B alignment
    int tid = threadIdx.x;
    int lr = tid / GG, lc = tid % GG;
    bool act = (tid < 5 * GG) && (r0 + lr < GG);

    float acc[50];
#pragma unroll
    for (int i = 0; i < 50; i++) acc[i] = 0.f;

    for (int ci = 0; ci < HID; ci++) {
        __syncthreads();
        for (int i = tid; i < 7 * 51; i += 256) {
            int rr = i / 51, cc = i % 51;
            int gr = r0 + rr - 1, gc = cc - 1;
            float v = 0.f;
            if (gr >= 0 && gr < GG && gc >= 0 && gc < GG)
                v = g_h1[(b * HID + ci) * GG * GG + gr * GG + gc];
            tile[i] = v;
        }
        for (int i = tid; i < 450; i += 256) {
            int co = i / 9, k = i % 9;
            ws[k * 52 + co] = w[(cob + co) * (HID * 9) + ci * 9 + k];
        }
        __syncthreads();
        if (act) {
#pragma unroll
            for (int k = 0; k < 9; k++) {
                float pk = tile[(lr + k / 3) * 51 + (lc + k % 3)];
                const float2* wp = (const float2*)&ws[k * 52];
#pragma unroll
                for (int j = 0; j < 25; j++) {
                    float2 w2 = wp[j];
                    acc[2 * j]     = fmaf(pk, w2.x, acc[2 * j]);
                    acc[2 * j + 1] = fmaf(pk, w2.y, acc[2 * j + 1]);
                }
            }
        }
    }
    if (act) {
        int gr = r0 + lr;
#pragma unroll
        for (int co = 0; co < 50; co++) {
            float v = fmaxf(acc[co] + bias[cob + co], 0.f);
            g_h2[(b * HID + cob + co) * GG * GG + gr * GG + lc] = v;
        }
    }
}

// ---------------- trans (72ch) + reward (1ch) conv, pad=2, out 51x51; softmax fused ----------------
__global__ __launch_bounds__(256) void trans_kernel(const float* __restrict__ tw,
                                                    const float* __restrict__ rw) {
    int b = blockIdx.y;
    int r0 = blockIdx.x * 5;
    __shared__ float tile[7 * 53];          // input rows r0-2..r0+4, cols -2..50
    __shared__ float ws[9 * 74];            // [k][ch 0..72]
    int tid = threadIdx.x;
    int lr = tid / HP, lc = tid % HP;
    bool act = (tid < 5 * HP) && (r0 + lr < HP);

    float acc[73];
#pragma unroll
    for (int i = 0; i < 73; i++) acc[i] = 0.f;

    for (int ci = 0; ci < HID; ci++) {
        __syncthreads();
        for (int i = tid; i < 7 * 53; i += 256) {
            int rr = i / 53, cc = i % 53;
            int gr = r0 - 2 + rr, gc = cc - 2;
            float v = 0.f;
            if (gr >= 0 && gr < GG && gc >= 0 && gc < GG)
                v = g_h2[(b * HID + ci) * GG * GG + gr * GG + gc];
            tile[i] = v;
        }
        for (int i = tid; i < 73 * 9; i += 256) {
            int ch = i / 9, k = i % 9;
            float v = (ch < 72) ? tw[ch * (HID * 9) + ci * 9 + k] : rw[ci * 9 + k];
            ws[k * 74 + ch] = v;
        }
        __syncthreads();
        if (act) {
#pragma unroll
            for (int k = 0; k < 9; k++) {
                float pk = tile[(lr + k / 3) * 53 + (lc + k % 3)];
                const float2* wp = (const float2*)&ws[k * 74];
#pragma unroll
                for (int j = 0; j < 36; j++) {
                    float2 w2 = wp[j];
                    acc[2 * j]     = fmaf(pk, w2.x, acc[2 * j]);
                    acc[2 * j + 1] = fmaf(pk, w2.y, acc[2 * j + 1]);
                }
                acc[72] = fmaf(pk, ws[k * 74 + 72], acc[72]);
            }
        }
    }
    if (act) {
        int gr = r0 + lr;
        int p = gr * HP + lc;
#pragma unroll
        for (int a = 0; a < AA; a++) {
            float m = acc[a * 9];
#pragma unroll
            for (int k = 1; k < 9; k++) m = fmaxf(m, acc[a * 9 + k]);
            float e[9];
            float s = 0.f;
#pragma unroll
            for (int k = 0; k < 9; k++) { e[k] = expf(acc[a * 9 + k] - m); s += e[k]; }
            float inv = 1.0f / s;
#pragma unroll
            for (int k = 0; k < 9; k++)
                g_sT[((b * AA + a) * 9 + k) * (HP * HP) + p] = e[k] * inv;
        }
        g_reward[b * HP * HP + p] = acc[72];
    }
}

// ---------------- VI loop: persistent CTA per batch item, 30 iterations ----------------
__global__ __launch_bounds__(512) void vi_kernel() {
    int b = blockIdx.x;
    __shared__ float vpad[53 * 53];         // v with 1-wide zero border
    __shared__ float rsh[HP * HP];
    int tid = threadIdx.x;
    for (int i = tid; i < 53 * 53; i += 512) vpad[i] = 0.f;
    for (int i = tid; i < HP * HP; i += 512) rsh[i] = g_reward[b * HP * HP + i];
    const float* __restrict__ sb = &g_sT[(size_t)b * AA * 9 * HP * HP];

    for (int it = 0; it < KK; it++) {
        __syncthreads();
        float vnew[6];
#pragma unroll
        for (int j = 0; j < 6; j++) {
            int p = tid + j * 512;
            if (p < HP * HP) {
                int r = p / HP, c = p % HP;
                float patch[9];
#pragma unroll
                for (int k = 0; k < 9; k++)
                    patch[k] = vpad[(r + k / 3) * 53 + (c + k % 3)];
                float rwv = rsh[p];
                float vm = -3.4e38f;
#pragma unroll
                for (int a = 0; a < AA; a++) {
                    float q = rwv;
#pragma unroll
                    for (int k = 0; k < 9; k++)
                        q = fmaf(sb[(a * 9 + k) * (HP * HP) + p], patch[k], q);
                    vm = fmaxf(vm, q);
                    if (it == KK - 1 && r < GG && c < GG)
                        g_qc[((b * AA + a) * GG + r) * GG + c] = q;
                }
                vnew[j] = vm;
            }
        }
        __syncthreads();
#pragma unroll
        for (int j = 0; j < 6; j++) {
            int p = tid + j * 512;
            if (p < HP * HP) {
                int r = p / HP, c = p % HP;
                vpad[(r + 1) * 53 + (c + 1)] = vnew[j];
            }
        }
    }
}

// ---------------- head: per-pixel 8 -> 150 (relu) -> 8 MLP ----------------
__global__ __launch_bounds__(256) void head_kernel(const float* __restrict__ w1,
                                                   const float* __restrict__ b1g,
                                                   const float* __restrict__ w2,
                                                   const float* __restrict__ b2g,
                                                   float* __restrict__ out) {
    int b = blockIdx.y;
    int p = blockIdx.x * 256 + threadIdx.x;
    __shared__ float w1s[HID * AA];         // [c][a]
    __shared__ float b1s[HID];
    __shared__ float w2s[HID * AA];         // transposed to [c][a]
    __shared__ float b2s[AA];
    int tid = threadIdx.x;
    for (int i = tid; i < HID * AA; i += 256) w1s[i] = w1[i];
    for (int i = tid; i < HID; i += 256) b1s[i] = b1g[i];
    for (int i = tid; i < HID * AA; i += 256) {
        int a = i / HID, c = i % HID;
        w2s[c * AA + a] = w2[i];
    }
    for (int i = tid; i < AA; i += 256) b2s[i] = b2g[i];
    __syncthreads();
    if (p >= GG * GG) return;

    float qv[AA];
#pragma unroll
    for (int a = 0; a < AA; a++) qv[a] = g_qc[(b * AA + a) * GG * GG + p];
    float o[AA];
#pragma unroll
    for (int a = 0; a < AA; a++) o[a] = b2s[a];

    for (int c = 0; c < HID; c++) {
        const float2* wp1 = (const float2*)&w1s[c * 8];
        float m = b1s[c];
#pragma unroll
        for (int j = 0; j < 4; j++) {
            float2 ww = wp1[j];
            m = fmaf(qv[2 * j], ww.x, m);
            m = fmaf(qv[2 * j + 1], ww.y, m);
        }
        m = fmaxf(m, 0.f);
        const float2* wp2 = (const float2*)&w2s[c * 8];
#pragma unroll
        for (int j = 0; j < 4; j++) {
            float2 ww = wp2[j];
            o[2 * j]     = fmaf(m, ww.x, o[2 * j]);
            o[2 * j + 1] = fmaf(m, ww.y, o[2 * j + 1]);
        }
    }
#pragma unroll
    for (int a = 0; a < AA; a++)
        out[(b * AA + a) * GG * GG + p] = o[a];
}

// ---------------- launch ----------------
extern "C" void kernel_launch(void* const* d_in, const int* in_sizes, int n_in,
                              void* d_out, int out_size) {
    const float* grid_in = (const float*)d_in[0];
    // d_in[1] = x_coord, d_in[2] = y_coord: unused by the reference
    const float* h1_w = (const float*)d_in[3];
    const float* h1_b = (const float*)d_in[4];
    const float* h2_w = (const float*)d_in[5];
    const float* h2_b = (const float*)d_in[6];
    const float* r_w  = (const float*)d_in[7];
    const float* t_w  = (const float*)d_in[8];
    const float* a1_w = (const float*)d_in[9];
    const float* a1_b = (const float*)d_in[10];
    const float* a2_w = (const float*)d_in[11];
    const float* a2_b = (const float*)d_in[12];

    conv1_kernel<<<dim3(7, BB), 256>>>(grid_in, h1_w, h1_b);
    conv2_kernel<<<dim3(10, 3, BB), 256>>>(h2_w, h2_b);
    trans_kernel<<<dim3(11, BB), 256>>>(t_w, r_w);
    vi_kernel<<<BB, 512>>>();
    head_kernel<<<dim3(10, BB), 256>>>(a1_w, a1_b, a2_w, a2_b, (float*)d_out);
}

// round 5
// speedup vs baseline: 1.7119x; 1.7119x over previous
#include <cuda_runtime.h>

#define GG  49
#define HP  51
#define HID 150
#define BB  128
#define CC  2
#define AA  8
#define KK  30
#define CI_BLK 10

// ---------------- scratch (static device globals; no allocation) ----------------
__device__ float g_h1[BB * HID * GG * GG];
__device__ float g_h2[BB * HID * GG * GG];
__device__ float g_sT[BB * AA * 9 * HP * HP];
__device__ float g_reward[BB * HP * HP];
__device__ float g_qc[BB * AA * GG * GG];

// ---------------- conv1: grid[B,2,49,49] -> relu -> h1[B,150,49,49] ----------------
__global__ __launch_bounds__(256) void conv1_kernel(const float* __restrict__ gin,
                                                    const float* __restrict__ w,
                                                    const float* __restrict__ bias) {
    int b = blockIdx.y;
    int r0 = blockIdx.x * 7;
    __shared__ float tile[CC * 9 * 51];
    __shared__ float ws[HID * 18];
    __shared__ float bs[HID];
    int tid = threadIdx.x;

    for (int i = tid; i < CC * 9 * 51; i += 256) {
        int ci = i / (9 * 51);
        int rr = (i / 51) % 9;
        int cc = i % 51;
        int gr = r0 + rr - 1, gc = cc - 1;
        float v = 0.f;
        if (gr >= 0 && gr < GG && gc >= 0 && gc < GG)
            v = gin[(b * CC + ci) * GG * GG + gr * GG + gc];
        tile[i] = v;
    }
    for (int i = tid; i < HID * 18; i += 256) ws[i] = w[i];
    for (int i = tid; i < HID; i += 256) bs[i] = bias[i];
    __syncthreads();

    for (int pp = tid; pp < 7 * GG; pp += 256) {
        int lr = pp / GG, lc = pp % GG;
        int gr = r0 + lr;
        if (gr >= GG) continue;
        float patch[18];
#pragma unroll
        for (int ci = 0; ci < CC; ci++)
#pragma unroll
            for (int k = 0; k < 9; k++)
                patch[ci * 9 + k] = tile[ci * 9 * 51 + (lr + k / 3) * 51 + (lc + k % 3)];
        for (int co = 0; co < HID; co++) {
            float a = bs[co];
            const float2* wp = (const float2*)&ws[co * 18];
#pragma unroll
            for (int j = 0; j < 9; j++) {
                float2 w2 = wp[j];
                a = fmaf(patch[2 * j], w2.x, a);
                a = fmaf(patch[2 * j + 1], w2.y, a);
            }
            g_h1[(b * HID + co) * GG * GG + gr * GG + lc] = fmaxf(a, 0.f);
        }
    }
}

// ---------------- conv2: h1 -> relu -> h2  (register-tiled: 7 rows x 10 co per thread) ----------------
// CTA: (7-row block, 50-co block, batch). thread = (col 0..48, co-group 0..4).
__global__ __launch_bounds__(256) void conv2_kernel(const float* __restrict__ w,
                                                    const float* __restrict__ bias) {
    int b = blockIdx.z;
    int cob = blockIdx.y * 50;
    int r0 = blockIdx.x * 7;
    __shared__ __align__(16) float tile[CI_BLK * 9 * 51];   // [ci][9 rows][51 cols], row0 = r0-1
    __shared__ __align__(16) float ws[CI_BLK * 9 * 50];     // [ci][k][co]
    int tid = threadIdx.x;
    int col = tid % GG;
    int cog = tid / GG;
    bool act = tid < 5 * GG;

    float acc[7][10];
#pragma unroll
    for (int r = 0; r < 7; r++)
#pragma unroll
        for (int j = 0; j < 10; j++) acc[r][j] = 0.f;

    for (int cib = 0; cib < HID; cib += CI_BLK) {
        for (int i = tid; i < CI_BLK * 9 * 51; i += 256) {
            int ci = i / 459;
            int rem = i % 459;
            int rr = rem / 51, cc = rem % 51;
            int gr = r0 + rr - 1, gc = cc - 1;
            float v = 0.f;
            if (gr >= 0 && gr < GG && gc >= 0 && gc < GG)
                v = g_h1[(b * HID + cib + ci) * GG * GG + gr * GG + gc];
            tile[i] = v;
        }
        for (int i = tid; i < CI_BLK * 450; i += 256) {
            int ci = i / 450;
            int rem = i % 450;
            int k = rem / 50, co = rem % 50;
            ws[(ci * 9 + k) * 50 + co] = w[(cob + co) * (HID * 9) + (cib + ci) * 9 + k];
        }
        __syncthreads();
        if (act) {
            for (int ci = 0; ci < CI_BLK; ci++) {
                const float* tb = &tile[ci * 459 + col];
#pragma unroll
                for (int dc = 0; dc < 3; dc++) {
                    float p[9];
#pragma unroll
                    for (int r = 0; r < 9; r++) p[r] = tb[r * 51 + dc];
#pragma unroll
                    for (int dr = 0; dr < 3; dr++) {
                        const float2* wp = (const float2*)&ws[(ci * 9 + dr * 3 + dc) * 50 + cog * 10];
                        float2 w0 = wp[0], w1 = wp[1], w2 = wp[2], w3 = wp[3], w4 = wp[4];
#pragma unroll
                        for (int rr = 0; rr < 7; rr++) {
                            float pv = p[rr + dr];
                            acc[rr][0] = fmaf(pv, w0.x, acc[rr][0]);
                            acc[rr][1] = fmaf(pv, w0.y, acc[rr][1]);
                            acc[rr][2] = fmaf(pv, w1.x, acc[rr][2]);
                            acc[rr][3] = fmaf(pv, w1.y, acc[rr][3]);
                            acc[rr][4] = fmaf(pv, w2.x, acc[rr][4]);
                            acc[rr][5] = fmaf(pv, w2.y, acc[rr][5]);
                            acc[rr][6] = fmaf(pv, w3.x, acc[rr][6]);
                            acc[rr][7] = fmaf(pv, w3.y, acc[rr][7]);
                            acc[rr][8] = fmaf(pv, w4.x, acc[rr][8]);
                            acc[rr][9] = fmaf(pv, w4.y, acc[rr][9]);
                        }
                    }
                }
            }
        }
        __syncthreads();
    }
    if (act) {
#pragma unroll
        for (int j = 0; j < 10; j++) {
            float bv = bias[cob + cog * 10 + j];
#pragma unroll
            for (int rr = 0; rr < 7; rr++) {
                float v = fmaxf(acc[rr][j] + bv, 0.f);
                g_h2[(b * HID + cob + cog * 10 + j) * GG * GG + (r0 + rr) * GG + col] = v;
            }
        }
    }
}

// ---------------- trans (72ch) + reward conv, pad=2, softmax fused ----------------
// CTA: (3-row block, batch). thread = (col 0..50, group 0..8); group<8 owns one action's
// 9 softmax channels, group 8 computes reward (weights zero-padded to 9).
__global__ __launch_bounds__(512) void trans_kernel(const float* __restrict__ tw,
                                                    const float* __restrict__ rw) {
    int b = blockIdx.y;
    int r0 = blockIdx.x * 3;
    __shared__ __align__(16) float tile[CI_BLK * 5 * 53];   // [ci][5 rows][53 cols], row0 = r0-2, col0 = -2
    __shared__ __align__(16) float ws[CI_BLK * 9 * 81];     // [ci][k][ch 0..80], ch>=73 zero
    int tid = threadIdx.x;
    int col = tid % HP;
    int g = tid / HP;
    bool act = tid < 9 * HP;

    float acc[3][9];
#pragma unroll
    for (int r = 0; r < 3; r++)
#pragma unroll
        for (int j = 0; j < 9; j++) acc[r][j] = 0.f;

    for (int cib = 0; cib < HID; cib += CI_BLK) {
        for (int i = tid; i < CI_BLK * 5 * 53; i += 512) {
            int ci = i / 265;
            int rem = i % 265;
            int rr = rem / 53, cc = rem % 53;
            int gr = r0 + rr - 2, gc = cc - 2;
            float v = 0.f;
            if (gr >= 0 && gr < GG && gc >= 0 && gc < GG)
                v = g_h2[(b * HID + cib + ci) * GG * GG + gr * GG + gc];
            tile[i] = v;
        }
        for (int i = tid; i < CI_BLK * 9 * 81; i += 512) {
            int ci = i / 729;
            int rem = i % 729;
            int k = rem / 81, ch = rem % 81;
            float v = 0.f;
            if (ch < 72) v = tw[ch * (HID * 9) + (cib + ci) * 9 + k];
            else if (ch == 72) v = rw[(cib + ci) * 9 + k];
            ws[i] = v;
        }
        __syncthreads();
        if (act) {
            for (int ci = 0; ci < CI_BLK; ci++) {
                const float* tb = &tile[ci * 265 + col];
#pragma unroll
                for (int dc = 0; dc < 3; dc++) {
                    float p[5];
#pragma unroll
                    for (int r = 0; r < 5; r++) p[r] = tb[r * 53 + dc];
#pragma unroll
                    for (int dr = 0; dr < 3; dr++) {
                        const float* wv = &ws[(ci * 9 + dr * 3 + dc) * 81 + g * 9];
                        float w0 = wv[0], w1 = wv[1], w2 = wv[2], w3 = wv[3], w4 = wv[4];
                        float w5 = wv[5], w6 = wv[6], w7 = wv[7], w8 = wv[8];
#pragma unroll
                        for (int rr = 0; rr < 3; rr++) {
                            float pv = p[rr + dr];
                            acc[rr][0] = fmaf(pv, w0, acc[rr][0]);
                            acc[rr][1] = fmaf(pv, w1, acc[rr][1]);
                            acc[rr][2] = fmaf(pv, w2, acc[rr][2]);
                            acc[rr][3] = fmaf(pv, w3, acc[rr][3]);
                            acc[rr][4] = fmaf(pv, w4, acc[rr][4]);
                            acc[rr][5] = fmaf(pv, w5, acc[rr][5]);
                            acc[rr][6] = fmaf(pv, w6, acc[rr][6]);
                            acc[rr][7] = fmaf(pv, w7, acc[rr][7]);
                            acc[rr][8] = fmaf(pv, w8, acc[rr][8]);
                        }
                    }
                }
            }
        }
        __syncthreads();
    }
    if (act) {
#pragma unroll
        for (int rr = 0; rr < 3; rr++) {
            int p = (r0 + rr) * HP + col;
            if (g < 8) {
                float m = acc[rr][0];
#pragma unroll
                for (int j = 1; j < 9; j++) m = fmaxf(m, acc[rr][j]);
                float e[9];
                float s = 0.f;
#pragma unroll
                for (int j = 0; j < 9; j++) { e[j] = expf(acc[rr][j] - m); s += e[j]; }
                float inv = 1.0f / s;
#pragma unroll
                for (int j = 0; j < 9; j++)
                    g_sT[((b * AA + g) * 9 + j) * (HP * HP) + p] = e[j] * inv;
            } else {
                g_reward[b * HP * HP + p] = acc[rr][0];
            }
        }
    }
}

// ---------------- VI loop: persistent CTA per batch item, 30 iterations ----------------
__global__ __launch_bounds__(512) void vi_kernel() {
    int b = blockIdx.x;
    __shared__ float vpad[53 * 53];
    __shared__ float rsh[HP * HP];
    int tid = threadIdx.x;
    for (int i = tid; i < 53 * 53; i += 512) vpad[i] = 0.f;
    for (int i = tid; i < HP * HP; i += 512) rsh[i] = g_reward[b * HP * HP + i];
    const float* __restrict__ sb = &g_sT[(size_t)b * AA * 9 * HP * HP];

    for (int it = 0; it < KK; it++) {
        __syncthreads();
        float vnew[6];
#pragma unroll
        for (int j = 0; j < 6; j++) {
            int p = tid + j * 512;
            if (p < HP * HP) {
                int r = p / HP, c = p % HP;
                float patch[9];
#pragma unroll
                for (int k = 0; k < 9; k++)
                    patch[k] = vpad[(r + k / 3) * 53 + (c + k % 3)];
                float rwv = rsh[p];
                float vm = -3.4e38f;
#pragma unroll
                for (int a = 0; a < AA; a++) {
                    float q = rwv;
#pragma unroll
                    for (int k = 0; k < 9; k++)
                        q = fmaf(sb[(a * 9 + k) * (HP * HP) + p], patch[k], q);
                    vm = fmaxf(vm, q);
                    if (it == KK - 1 && r < GG && c < GG)
                        g_qc[((b * AA + a) * GG + r) * GG + c] = q;
                }
                vnew[j] = vm;
            }
        }
        __syncthreads();
#pragma unroll
        for (int j = 0; j < 6; j++) {
            int p = tid + j * 512;
            if (p < HP * HP) {
                int r = p / HP, c = p % HP;
                vpad[(r + 1) * 53 + (c + 1)] = vnew[j];
            }
        }
    }
}

// ---------------- head: per-pixel 8 -> 150 (relu) -> 8 MLP ----------------
__global__ __launch_bounds__(256) void head_kernel(const float* __restrict__ w1,
                                                   const float* __restrict__ b1g,
                                                   const float* __restrict__ w2,
                                                   const float* __restrict__ b2g,
                                                   float* __restrict__ out) {
    int b = blockIdx.y;
    int p = blockIdx.x * 256 + threadIdx.x;
    __shared__ float w1s[HID * AA];
    __shared__ float b1s[HID];
    __shared__ float w2s[HID * AA];
    __shared__ float b2s[AA];
    int tid = threadIdx.x;
    for (int i = tid; i < HID * AA; i += 256) w1s[i] = w1[i];
    for (int i = tid; i < HID; i += 256) b1s[i] = b1g[i];
    for (int i = tid; i < HID * AA; i += 256) {
        int a = i / HID, c = i % HID;
        w2s[c * AA + a] = w2[i];
    }
    for (int i = tid; i < AA; i += 256) b2s[i] = b2g[i];
    __syncthreads();
    if (p >= GG * GG) return;

    float qv[AA];
#pragma unroll
    for (int a = 0; a < AA; a++) qv[a] = g_qc[(b * AA + a) * GG * GG + p];
    float o[AA];
#pragma unroll
    for (int a = 0; a < AA; a++) o[a] = b2s[a];

    for (int c = 0; c < HID; c++) {
        const float2* wp1 = (const float2*)&w1s[c * 8];
        float m = b1s[c];
#pragma unroll
        for (int j = 0; j < 4; j++) {
            float2 ww = wp1[j];
            m = fmaf(qv[2 * j], ww.x, m);
            m = fmaf(qv[2 * j + 1], ww.y, m);
        }
        m = fmaxf(m, 0.f);
        const float2* wp2 = (const float2*)&w2s[c * 8];
#pragma unroll
        for (int j = 0; j < 4; j++) {
            float2 ww = wp2[j];
            o[2 * j]     = fmaf(m, ww.x, o[2 * j]);
            o[2 * j + 1] = fmaf(m, ww.y, o[2 * j + 1]);
        }
    }
#pragma unroll
    for (int a = 0; a < AA; a++)
        out[(b * AA + a) * GG * GG + p] = o[a];
}

// ---------------- launch ----------------
extern "C" void kernel_launch(void* const* d_in, const int* in_sizes, int n_in,
                              void* d_out, int out_size) {
    const float* grid_in = (const float*)d_in[0];
    const float* h1_w = (const float*)d_in[3];
    const float* h1_b = (const float*)d_in[4];
    const float* h2_w = (const float*)d_in[5];
    const float* h2_b = (const float*)d_in[6];
    const float* r_w  = (const float*)d_in[7];
    const float* t_w  = (const float*)d_in[8];
    const float* a1_w = (const float*)d_in[9];
    const float* a1_b = (const float*)d_in[10];
    const float* a2_w = (const float*)d_in[11];
    const float* a2_b = (const float*)d_in[12];

    conv1_kernel<<<dim3(7, BB), 256>>>(grid_in, h1_w, h1_b);
    conv2_kernel<<<dim3(7, 3, BB), 256>>>(h2_w, h2_b);
    trans_kernel<<<dim3(17, BB), 512>>>(t_w, r_w);
    vi_kernel<<<BB, 512>>>();
    head_kernel<<<dim3(10, BB), 256>>>(a1_w, a1_b, a2_w, a2_b, (float*)d_out);
}

// round 7
// speedup vs baseline: 1.9333x; 1.1294x over previous
#include <cuda_runtime.h>

#define GG  49
#define HP  51
#define HID 150
#define BB  128
#define CC  2
#define AA  8
#define KK  30
#define CI_BLK 10

typedef unsigned long long u64;

__device__ __forceinline__ u64 pack2(float x, float y) {
    u64 r; asm("mov.b64 %0, {%1,%2};" : "=l"(r) : "f"(x), "f"(y)); return r;
}
__device__ __forceinline__ void ffma2(u64& acc, u64 a, u64 b) {
    asm("fma.rn.f32x2 %0, %1, %2, %0;" : "+l"(acc) : "l"(a), "l"(b));
}
__device__ __forceinline__ float2 unpack2(u64 v) {
    float2 f; asm("mov.b64 {%0,%1}, %2;" : "=f"(f.x), "=f"(f.y) : "l"(v)); return f;
}

// ---------------- scratch (static device globals; no allocation) ----------------
__device__ float g_h1[BB * HID * GG * GG];
__device__ float g_h2[BB * HID * GG * GG];
__device__ float g_sT[BB * AA * 9 * HP * HP];
__device__ float g_reward[BB * HP * HP];
__device__ float g_qc[BB * AA * GG * GG];

// ---------------- conv1: grid[B,2,49,49] -> relu -> h1[B,150,49,49] ----------------
__global__ __launch_bounds__(256) void conv1_kernel(const float* __restrict__ gin,
                                                    const float* __restrict__ w,
                                                    const float* __restrict__ bias) {
    int b = blockIdx.y;
    int r0 = blockIdx.x * 7;
    __shared__ float tile[CC * 9 * 51];
    __shared__ float ws[HID * 18];
    __shared__ float bs[HID];
    int tid = threadIdx.x;

    for (int i = tid; i < CC * 9 * 51; i += 256) {
        int ci = i / (9 * 51);
        int rr = (i / 51) % 9;
        int cc = i % 51;
        int gr = r0 + rr - 1, gc = cc - 1;
        float v = 0.f;
        if (gr >= 0 && gr < GG && gc >= 0 && gc < GG)
            v = gin[(b * CC + ci) * GG * GG + gr * GG + gc];
        tile[i] = v;
    }
    for (int i = tid; i < HID * 18; i += 256) ws[i] = w[i];
    for (int i = tid; i < HID; i += 256) bs[i] = bias[i];
    __syncthreads();

    for (int pp = tid; pp < 7 * GG; pp += 256) {
        int lr = pp / GG, lc = pp % GG;
        int gr = r0 + lr;
        if (gr >= GG) continue;
        float patch[18];
#pragma unroll
        for (int ci = 0; ci < CC; ci++)
#pragma unroll
            for (int k = 0; k < 9; k++)
                patch[ci * 9 + k] = tile[ci * 9 * 51 + (lr + k / 3) * 51 + (lc + k % 3)];
        for (int co = 0; co < HID; co++) {
            float a = bs[co];
            const float2* wp = (const float2*)&ws[co * 18];
#pragma unroll
            for (int j = 0; j < 9; j++) {
                float2 w2 = wp[j];
                a = fmaf(patch[2 * j], w2.x, a);
                a = fmaf(patch[2 * j + 1], w2.y, a);
            }
            g_h1[(b * HID + co) * GG * GG + gr * GG + lc] = fmaxf(a, 0.f);
        }
    }
}

// ---------------- conv2: register-tiled 7 rows x 10 co, packed f32x2 FMA ----------------
__global__ __launch_bounds__(256) void conv2_kernel(const float* __restrict__ w,
                                                    const float* __restrict__ bias) {
    int b = blockIdx.z;
    int cob = blockIdx.y * 50;
    int r0 = blockIdx.x * 7;
    __shared__ __align__(16) float tile[CI_BLK * 9 * 51];   // [ci][9 rows][51 cols], row0 = r0-1
    __shared__ __align__(16) float ws[CI_BLK * 9 * 50];     // [ci][k][co]
    int tid = threadIdx.x;
    int col = tid % GG;
    int cog = tid / GG;
    bool act = tid < 5 * GG;

    u64 acc[7][5];                                          // 7 rows x 5 co-pairs
#pragma unroll
    for (int r = 0; r < 7; r++)
#pragma unroll
        for (int j = 0; j < 5; j++) acc[r][j] = 0ULL;

    for (int cib = 0; cib < HID; cib += CI_BLK) {
        for (int i = tid; i < CI_BLK * 9 * 51; i += 256) {
            int ci = i / 459;
            int rem = i % 459;
            int rr = rem / 51, cc = rem % 51;
            int gr = r0 + rr - 1, gc = cc - 1;
            float v = 0.f;
            if (gr >= 0 && gr < GG && gc >= 0 && gc < GG)
                v = g_h1[(b * HID + cib + ci) * GG * GG + gr * GG + gc];
            tile[i] = v;
        }
        for (int i = tid; i < CI_BLK * 450; i += 256) {
            int ci = i / 450;
            int rem = i % 450;
            int k = rem / 50, co = rem % 50;
            ws[(ci * 9 + k) * 50 + co] = w[(cob + co) * (HID * 9) + (cib + ci) * 9 + k];
        }
        __syncthreads();
        if (act) {
            for (int ci = 0; ci < CI_BLK; ci++) {
                const float* tb = &tile[ci * 459 + col];
#pragma unroll
                for (int dc = 0; dc < 3; dc++) {
                    u64 pp[9];
#pragma unroll
                    for (int r = 0; r < 9; r++) {
                        float pv = tb[r * 51 + dc];
                        pp[r] = pack2(pv, pv);
                    }
#pragma unroll
                    for (int dr = 0; dr < 3; dr++) {
                        const u64* wp = (const u64*)&ws[(ci * 9 + dr * 3 + dc) * 50 + cog * 10];
                        u64 w0 = wp[0], w1 = wp[1], w2 = wp[2], w3 = wp[3], w4 = wp[4];
#pragma unroll
                        for (int rr = 0; rr < 7; rr++) {
                            u64 pv = pp[rr + dr];
                            ffma2(acc[rr][0], pv, w0);
                            ffma2(acc[rr][1], pv, w1);
                            ffma2(acc[rr][2], pv, w2);
                            ffma2(acc[rr][3], pv, w3);
                            ffma2(acc[rr][4], pv, w4);
                        }
                    }
                }
            }
        }
        __syncthreads();
    }
    if (act) {
#pragma unroll
        for (int j = 0; j < 5; j++) {
            float b0 = bias[cob + cog * 10 + 2 * j];
            float b1 = bias[cob + cog * 10 + 2 * j + 1];
#pragma unroll
            for (int rr = 0; rr < 7; rr++) {
                float2 v = unpack2(acc[rr][j]);
                float v0 = fmaxf(v.x + b0, 0.f);
                float v1 = fmaxf(v.y + b1, 0.f);
                size_t base = (size_t)(b * HID + cob + cog * 10) * GG * GG + (r0 + rr) * GG + col;
                g_h2[base + (size_t)(2 * j) * GG * GG]     = v0;
                g_h2[base + (size_t)(2 * j + 1) * GG * GG] = v1;
            }
        }
    }
}

// ---------------- trans (72ch) + reward conv, pad=2, softmax fused, packed f32x2 ----------------
// thread = (col 0..50, group 0..8); group<8 owns one action's 9 softmax channels,
// group 8 computes reward. Weight smem stride 10 per group for 8B-aligned pair loads.
__global__ __launch_bounds__(512) void trans_kernel(const float* __restrict__ tw,
                                                    const float* __restrict__ rw) {
    int b = blockIdx.y;
    int r0 = blockIdx.x * 3;
    __shared__ __align__(16) float tile[CI_BLK * 5 * 53];   // [ci][5 rows][53 cols], row0=r0-2, col0=-2
    __shared__ __align__(16) float ws[CI_BLK * 9 * 90];     // [ci][k][group*10 + j], j=9 pad=0
    int tid = threadIdx.x;
    int col = tid % HP;
    int g = tid / HP;
    bool act = tid < 9 * HP;

    u64   acc[3][4];                                        // 4 channel-pairs (j 0..7)
    float acc8[3];                                          // channel j=8
#pragma unroll
    for (int r = 0; r < 3; r++) {
#pragma unroll
        for (int j = 0; j < 4; j++) acc[r][j] = 0ULL;
        acc8[r] = 0.f;
    }

    for (int cib = 0; cib < HID; cib += CI_BLK) {
        for (int i = tid; i < CI_BLK * 5 * 53; i += 512) {
            int ci = i / 265;
            int rem = i % 265;
            int rr = rem / 53, cc = rem % 53;
            int gr = r0 + rr - 2, gc = cc - 2;
            float v = 0.f;
            if (gr >= 0 && gr < GG && gc >= 0 && gc < GG)
                v = g_h2[(b * HID + cib + ci) * GG * GG + gr * GG + gc];
            tile[i] = v;
        }
        for (int i = tid; i < CI_BLK * 9 * 90; i += 512) {
            int ci = i / 810;
            int rem = i % 810;
            int k = rem / 90, chp = rem % 90;
            int gg2 = chp / 10, j = chp % 10;
            float v = 0.f;
            if (j < 9) {
                int ch = gg2 * 9 + j;
                if (ch < 72) v = tw[ch * (HID * 9) + (cib + ci) * 9 + k];
                else if (ch == 72) v = rw[(cib + ci) * 9 + k];
            }
            ws[(ci * 9 + k) * 90 + chp] = v;
        }
        __syncthreads();
        if (act) {
            for (int ci = 0; ci < CI_BLK; ci++) {
                const float* tb = &tile[ci * 265 + col];
#pragma unroll
                for (int dc = 0; dc < 3; dc++) {
                    u64 pp[5];
                    float pf[5];
#pragma unroll
                    for (int r = 0; r < 5; r++) {
                        pf[r] = tb[r * 53 + dc];
                        pp[r] = pack2(pf[r], pf[r]);
                    }
#pragma unroll
                    for (int dr = 0; dr < 3; dr++) {
                        const float* wvf = &ws[(ci * 9 + dr * 3 + dc) * 90 + g * 10];
                        const u64* wp = (const u64*)wvf;
                        u64 w0 = wp[0], w1 = wp[1], w2 = wp[2], w3 = wp[3];
                        float w8 = wvf[8];
#pragma unroll
                        for (int rr = 0; rr < 3; rr++) {
                            u64 pv = pp[rr + dr];
                            ffma2(acc[rr][0], pv, w0);
                            ffma2(acc[rr][1], pv, w1);
                            ffma2(acc[rr][2], pv, w2);
                            ffma2(acc[rr][3], pv, w3);
                            acc8[rr] = fmaf(pf[rr + dr], w8, acc8[rr]);
                        }
                    }
                }
            }
        }
        __syncthreads();
    }
    if (act) {
#pragma unroll
        for (int rr = 0; rr < 3; rr++) {
            int p = (r0 + rr) * HP + col;
            float av[9];
#pragma unroll
            for (int j = 0; j < 4; j++) {
                float2 v = unpack2(acc[rr][j]);
                av[2 * j] = v.x;
                av[2 * j + 1] = v.y;
            }
            av[8] = acc8[rr];
            if (g < 8) {
                float m = av[0];
#pragma unroll
                for (int j = 1; j < 9; j++) m = fmaxf(m, av[j]);
                float e[9];
                float s = 0.f;
#pragma unroll
                for (int j = 0; j < 9; j++) { e[j] = expf(av[j] - m); s += e[j]; }
                float inv = 1.0f / s;
#pragma unroll
                for (int j = 0; j < 9; j++)
                    g_sT[((b * AA + g) * 9 + j) * (HP * HP) + p] = e[j] * inv;
            } else {
                g_reward[b * HP * HP + p] = av[0];
            }
        }
    }
}

// ---------------- VI loop: persistent CTA per batch item, 30 iterations ----------------
__global__ __launch_bounds__(1024) void vi_kernel() {
    int b = blockIdx.x;
    __shared__ float vpad[53 * 53];
    __shared__ float rsh[HP * HP];
    int tid = threadIdx.x;
    for (int i = tid; i < 53 * 53; i += 1024) vpad[i] = 0.f;
    for (int i = tid; i < HP * HP; i += 1024) rsh[i] = g_reward[b * HP * HP + i];
    const float* __restrict__ sb = &g_sT[(size_t)b * AA * 9 * HP * HP];

    for (int it = 0; it < KK; it++) {
        __syncthreads();
        float vnew[3];
#pragma unroll
        for (int j = 0; j < 3; j++) {
            int p = tid + j * 1024;
            if (p < HP * HP) {
                int r = p / HP, c = p % HP;
                float patch[9];
#pragma unroll
                for (int k = 0; k < 9; k++)
                    patch[k] = vpad[(r + k / 3) * 53 + (c + k % 3)];
                float rwv = rsh[p];
                float vm = -3.4e38f;
#pragma unroll
                for (int a = 0; a < AA; a++) {
                    float q = rwv;
#pragma unroll
                    for (int k = 0; k < 9; k++)
                        q = fmaf(sb[(a * 9 + k) * (HP * HP) + p], patch[k], q);
                    vm = fmaxf(vm, q);
                    if (it == KK - 1 && r < GG && c < GG)
                        g_qc[((b * AA + a) * GG + r) * GG + c] = q;
                }
                vnew[j] = vm;
            }
        }
        __syncthreads();
#pragma unroll
        for (int j = 0; j < 3; j++) {
            int p = tid + j * 1024;
            if (p < HP * HP) {
                int r = p / HP, c = p % HP;
                vpad[(r + 1) * 53 + (c + 1)] = vnew[j];
            }
        }
    }
}

// ---------------- head: per-pixel 8 -> 150 (relu) -> 8 MLP ----------------
__global__ __launch_bounds__(256) void head_kernel(const float* __restrict__ w1,
                                                   const float* __restrict__ b1g,
                                                   const float* __restrict__ w2,
                                                   const float* __restrict__ b2g,
                                                   float* __restrict__ out) {
    int b = blockIdx.y;
    int p = blockIdx.x * 256 + threadIdx.x;
    __shared__ float w1s[HID * AA];
    __shared__ float b1s[HID];
    __shared__ float w2s[HID * AA];
    __shared__ float b2s[AA];
    int tid = threadIdx.x;
    for (int i = tid; i < HID * AA; i += 256) w1s[i] = w1[i];
    for (int i = tid; i < HID; i += 256) b1s[i] = b1g[i];
    for (int i = tid; i < HID * AA; i += 256) {
        int a = i / HID, c = i % HID;
        w2s[c * AA + a] = w2[i];
    }
    for (int i = tid; i < AA; i += 256) b2s[i] = b2g[i];
    __syncthreads();
    if (p >= GG * GG) return;

    float qv[AA];
#pragma unroll
    for (int a = 0; a < AA; a++) qv[a] = g_qc[(b * AA + a) * GG * GG + p];
    float o[AA];
#pragma unroll
    for (int a = 0; a < AA; a++) o[a] = b2s[a];

    for (int c = 0; c < HID; c++) {
        const float2* wp1 = (const float2*)&w1s[c * 8];
        float m = b1s[c];
#pragma unroll
        for (int j = 0; j < 4; j++) {
            float2 ww = wp1[j];
            m = fmaf(qv[2 * j], ww.x, m);
            m = fmaf(qv[2 * j + 1], ww.y, m);
        }
        m = fmaxf(m, 0.f);
        const float2* wp2 = (const float2*)&w2s[c * 8];
#pragma unroll
        for (int j = 0; j < 4; j++) {
            float2 ww = wp2[j];
            o[2 * j]     = fmaf(m, ww.x, o[2 * j]);
            o[2 * j + 1] = fmaf(m, ww.y, o[2 * j + 1]);
        }
    }
#pragma unroll
    for (int a = 0; a < AA; a++)
        out[(b * AA + a) * GG * GG + p] = o[a];
}

// ---------------- launch ----------------
extern "C" void kernel_launch(void* const* d_in, const int* in_sizes, int n_in,
                              void* d_out, int out_size) {
    const float* grid_in = (const float*)d_in[0];
    const float* h1_w = (const float*)d_in[3];
    const float* h1_b = (const float*)d_in[4];
    const float* h2_w = (const float*)d_in[5];
    const float* h2_b = (const float*)d_in[6];
    const float* r_w  = (const float*)d_in[7];
    const float* t_w  = (const float*)d_in[8];
    const float* a1_w = (const float*)d_in[9];
    const float* a1_b = (const float*)d_in[10];
    const float* a2_w = (const float*)d_in[11];
    const float* a2_b = (const float*)d_in[12];

    conv1_kernel<<<dim3(7, BB), 256>>>(grid_in, h1_w, h1_b);
    conv2_kernel<<<dim3(7, 3, BB), 256>>>(h2_w, h2_b);
    trans_kernel<<<dim3(17, BB), 512>>>(t_w, r_w);
    vi_kernel<<<BB, 1024>>>();
    head_kernel<<<dim3(10, BB), 256>>>(a1_w, a1_b, a2_w, a2_b, (float*)d_out);
}